// round 15
// baseline (speedup 1.0000x reference)
#include <cuda_runtime.h>
#include <cuda_bf16.h>
#include <cstdint>

#define BB 4
#define SS 256
#define HH 768
#define N2 1536
#define MM 1024
#define NPAIR 32896

// GEMM tiling: BM=64, BN=128, split-K=2 (each producer CTA does K=384)
#define BM 64
#define BN 128
#define BK 32
#define RS 40                   // smem row stride in bf16 elems (80B, padded, conflict-free)
#define APLANE (BM * RS)        // 2560
#define BPLANE (BN * RS)        // 5120
#define BUFSZ (2 * APLANE + 2 * BPLANE)   // 15360 elems (30720 B) per buffer
#define NCH 12                  // chunks per K-split (384/32)
#define GEMM_SMEM (2 * BUFSZ * (int)sizeof(uint16_t))   // 61440 B
#define NTILE 528               // per-batch upper-triangular 8x8 tile count
#define BLK (96 + NTILE)        // bids per batch block: 96 producers + 528 consumers

__device__ float g_gv[2][MM * N2];      // two split-K planes; [m][0:768)=g, [768:)=v
__device__ int g_cnt[16];               // per (batch, 64-row group) counters, target 24
__device__ __nv_bfloat16 g_Ahi[MM * HH];
__device__ __nv_bfloat16 g_Alo[MM * HH];
__device__ __nv_bfloat16 g_Bhi[N2 * HH];   // [n][k], n<768 -> Wg row, n>=768 -> Wv row
__device__ __nv_bfloat16 g_Blo[N2 * HH];

// ---------------------------------------------------------------------------
// helpers
// ---------------------------------------------------------------------------
__device__ __forceinline__ uint32_t smem_u32(const void* p) {
    uint32_t a;
    asm("{ .reg .u64 t; cvta.to.shared.u64 t, %1; cvt.u32.u64 %0, t; }" : "=r"(a) : "l"(p));
    return a;
}

__device__ __forceinline__ void cp16(uint32_t dst, const void* src) {
    asm volatile("cp.async.cg.shared.global [%0], [%1], 16;" :: "r"(dst), "l"(src));
}
#define CP_COMMIT() asm volatile("cp.async.commit_group;" ::: "memory")
#define CP_WAIT1()  asm volatile("cp.async.wait_group 1;" ::: "memory")
#define CP_WAIT0()  asm volatile("cp.async.wait_group 0;" ::: "memory")

__device__ __forceinline__ void ldsm_x4(uint32_t* r, uint32_t addr) {
    asm volatile("ldmatrix.sync.aligned.m8n8.x4.shared.b16 {%0,%1,%2,%3}, [%4];"
                 : "=r"(r[0]), "=r"(r[1]), "=r"(r[2]), "=r"(r[3]) : "r"(addr));
}

__device__ __forceinline__ void mma16816(float* c, const uint32_t* a, const uint32_t* b) {
    asm volatile(
        "mma.sync.aligned.m16n8k16.row.col.f32.bf16.bf16.f32 "
        "{%0,%1,%2,%3}, {%4,%5,%6,%7}, {%8,%9}, {%0,%1,%2,%3};"
        : "+f"(c[0]), "+f"(c[1]), "+f"(c[2]), "+f"(c[3])
        : "r"(a[0]), "r"(a[1]), "r"(a[2]), "r"(a[3]), "r"(b[0]), "r"(b[1]));
}

__device__ __forceinline__ float fast_tanh(float x) {
    float y;
    asm("tanh.approx.f32 %0, %1;" : "=f"(y) : "f"(x));
    return y;
}

__device__ __forceinline__ int ld_acq(const int* p) {
    int v;
    asm volatile("ld.acquire.gpu.b32 %0, [%1];" : "=r"(v) : "l"(p) : "memory");
    return v;
}

__device__ __forceinline__ void split_pack(float a, float b, uint32_t& hi, uint32_t& lo) {
    asm("cvt.rn.bf16x2.f32 %0, %1, %2;" : "=r"(hi) : "f"(b), "f"(a));
    float ha = __uint_as_float(hi << 16);
    float hb = __uint_as_float(hi & 0xffff0000u);
    asm("cvt.rn.bf16x2.f32 %0, %1, %2;" : "=r"(lo) : "f"(b - hb), "f"(a - ha));
}

// ---------------------------------------------------------------------------
// Convert: fp32 X,W -> bf16 hi/lo planes; also zero the sync counters.
// ---------------------------------------------------------------------------
__global__ __launch_bounds__(256) void convert_kernel(
    const float* __restrict__ X, const float* __restrict__ W)
{
    if (blockIdx.x == 0 && threadIdx.x < 16) g_cnt[threadIdx.x] = 0;

    const int NX4 = MM * HH / 4;   // 196608
    const int NW4 = N2 * HH / 4;   // 294912
    int i4 = blockIdx.x * blockDim.x + threadIdx.x;
    if (i4 < NX4) {
        float4 v = ((const float4*)X)[i4];
        uint2 hv, lv;
        split_pack(v.x, v.y, hv.x, lv.x);
        split_pack(v.z, v.w, hv.y, lv.y);
        ((uint2*)g_Ahi)[i4] = hv;
        ((uint2*)g_Alo)[i4] = lv;
    } else if (i4 < NX4 + NW4) {
        int w4 = i4 - NX4;
        int e = w4 * 4;
        int n = e / HH;
        int k = e - n * HH;
        int o    = (n < HH) ? n : n - HH;
        int coff = (n < HH) ? 0 : HH;
        float4 v = *(const float4*)(W + (size_t)o * N2 + coff + k);
        uint2 hv, lv;
        split_pack(v.x, v.y, hv.x, lv.x);
        split_pack(v.z, v.w, hv.y, lv.y);
        ((uint2*)g_Bhi)[w4] = hv;
        ((uint2*)g_Blo)[w4] = lv;
    }
}

// ---------------------------------------------------------------------------
// Fused kernel. Per batch block of 624 bids:
//   [0,96):  GEMM producers (split-K=2, cp.async pipeline, bf16 3-pass)
//   [96,624): expand consumers (one upper-tri 8x8 tile each)
// ---------------------------------------------------------------------------
__global__ __launch_bounds__(256, 3) void fused_kernel(
    const float* __restrict__ bias, float* __restrict__ out)
{
    extern __shared__ char smx[];
    const int bid = blockIdx.x;
    const int tid = threadIdx.x;
    const int lane = tid & 31, wid = tid >> 5;
    const int b = bid / BLK;
    const int p = bid % BLK;

    if (p < 96) {
        // ================= GEMM producer =================
        const uint32_t sbase = smem_u32(smx);

        const int ksp = p / 48;
        const int tt  = p % 48;
        const int mt  = tt / 12;
        const int nt  = tt % 12;
        const int m0  = b * SS + mt * BM;
        const int n0  = nt * BN;
        const int kb0 = ksp * 384;
        const int side = (n0 >= HH) ? 1 : 0;

        const int mwB = (wid >> 2) * 32;
        const int nwB = (wid & 3) * 32;
        const int gr  = lane >> 2;
        const int gc  = (lane & 3) << 1;

        // ldmatrix lane addressing terms (bf16 elem units)
        const int lrow = lane & 7;
        const int q    = lane >> 3;
        int aTerm[2], bTerm[2];
#pragma unroll
        for (int m = 0; m < 2; m++)
            aTerm[m] = (mwB + m * 16 + (q & 1) * 8 + lrow) * RS + (q >> 1) * 8;
#pragma unroll
        for (int u = 0; u < 2; u++)
            bTerm[u] = (nwB + u * 16 + (q >> 1) * 8 + lrow) * RS + (q & 1) * 8;

        // cp.async slots: A (1 x16B per plane), B (2 x16B per plane)
        const int ar = tid >> 2, ac = tid & 3;
        const size_t aSrc = (size_t)(m0 + ar) * HH + kb0 + ac * 8;
        const uint32_t aDst = (uint32_t)(ar * RS + ac * 8) * 2;
        size_t bSrc[2];
        uint32_t bDst[2];
#pragma unroll
        for (int qq = 0; qq < 2; qq++) {
            int f = qq * 256 + tid;
            int r = f >> 2, c = f & 3;
            bSrc[qq] = (size_t)(n0 + r) * HH + kb0 + c * 8;
            bDst[qq] = (uint32_t)(r * RS + c * 8) * 2;
        }

        float acc[2][4][4] = {};

        // pipeline: issue chunk0
        {
            const uint32_t base = sbase;
            cp16(base + aDst, g_Ahi + aSrc);
            cp16(base + APLANE * 2 + aDst, g_Alo + aSrc);
#pragma unroll
            for (int qq = 0; qq < 2; qq++) {
                cp16(base + 2 * APLANE * 2 + bDst[qq], g_Bhi + bSrc[qq]);
                cp16(base + (2 * APLANE + BPLANE) * 2 + bDst[qq], g_Blo + bSrc[qq]);
            }
            CP_COMMIT();
        }

#pragma unroll 1
        for (int ch = 0; ch < NCH; ch++) {
            if (ch < NCH - 1) {
                const int ka = (ch + 1) * BK;
                const uint32_t base = sbase + (uint32_t)(((ch + 1) & 1) * BUFSZ) * 2;
                cp16(base + aDst, g_Ahi + aSrc + ka);
                cp16(base + APLANE * 2 + aDst, g_Alo + aSrc + ka);
#pragma unroll
                for (int qq = 0; qq < 2; qq++) {
                    cp16(base + 2 * APLANE * 2 + bDst[qq], g_Bhi + bSrc[qq] + ka);
                    cp16(base + (2 * APLANE + BPLANE) * 2 + bDst[qq], g_Blo + bSrc[qq] + ka);
                }
                CP_COMMIT();
                CP_WAIT1();
            } else {
                CP_WAIT0();
            }
            __syncthreads();

            const uint32_t Ah = sbase + (uint32_t)((ch & 1) * BUFSZ) * 2;
            const uint32_t Al = Ah + APLANE * 2;
            const uint32_t Bh = Al + APLANE * 2;
            const uint32_t Bl = Bh + BPLANE * 2;

#pragma unroll
            for (int ks = 0; ks < 2; ks++) {
                const uint32_t kbb = (uint32_t)(ks * 16) * 2;
                uint32_t ahi[2][4], bx[4][2], t4[4];
                // ahi + bhi, then mma; reload bx for blo; alo last (low live range)
#pragma unroll
                for (int m = 0; m < 2; m++)
                    ldsm_x4(ahi[m], Ah + (uint32_t)aTerm[m] * 2 + kbb);
#pragma unroll
                for (int u = 0; u < 2; u++) {
                    ldsm_x4(t4, Bh + (uint32_t)bTerm[u] * 2 + kbb);
                    bx[2 * u][0] = t4[0]; bx[2 * u][1] = t4[1];
                    bx[2 * u + 1][0] = t4[2]; bx[2 * u + 1][1] = t4[3];
                }
#pragma unroll
                for (int m = 0; m < 2; m++)
#pragma unroll
                    for (int n = 0; n < 4; n++) mma16816(acc[m][n], ahi[m], bx[n]);

                // alo x bhi (bx still holds bhi)
                {
                    uint32_t alo[4];
#pragma unroll
                    for (int m = 0; m < 2; m++) {
                        ldsm_x4(alo, Al + (uint32_t)aTerm[m] * 2 + kbb);
#pragma unroll
                        for (int n = 0; n < 4; n++) mma16816(acc[m][n], alo, bx[n]);
                    }
                }

                // ahi x blo (reload bx with blo)
#pragma unroll
                for (int u = 0; u < 2; u++) {
                    ldsm_x4(t4, Bl + (uint32_t)bTerm[u] * 2 + kbb);
                    bx[2 * u][0] = t4[0]; bx[2 * u][1] = t4[1];
                    bx[2 * u + 1][0] = t4[2]; bx[2 * u + 1][1] = t4[3];
                }
#pragma unroll
                for (int m = 0; m < 2; m++)
#pragma unroll
                    for (int n = 0; n < 4; n++) mma16816(acc[m][n], ahi[m], bx[n]);
            }
            __syncthreads();
        }

        // epilogue -> plane ksp; bias only on (g half, plane 0)
        float* plane = g_gv[ksp];
#pragma unroll
        for (int m = 0; m < 2; m++) {
#pragma unroll
            for (int n = 0; n < 4; n++) {
                const int r = m0 + mwB + m * 16 + gr;
                const int c = n0 + nwB + n * 8 + gc;
                float b0 = 0.f, b1 = 0.f;
                if (!side && ksp == 0) { b0 = bias[c]; b1 = bias[c + 1]; }
                float* pp = plane + (size_t)r * N2 + c;
                float2 v0, v1;
                v0.x = acc[m][n][0] + b0;
                v0.y = acc[m][n][1] + b1;
                v1.x = acc[m][n][2] + b0;
                v1.y = acc[m][n][3] + b1;
                *(float2*)pp = v0;
                *(float2*)(pp + 8 * N2) = v1;
            }
        }

        __threadfence();
        __syncthreads();
        if (tid == 0) atomicAdd(&g_cnt[b * 4 + mt], 1);

    } else {
        // ================= expand consumer =================
        constexpr int V4 = HH / 4;  // 192
        float* vs = (float*)smx;    // 8 rows * 768 floats = 24KB

        int r = p - 96;
        int ti = 0;
        while (r >= 32 - ti) { r -= 32 - ti; ti++; }
        const int tj = ti + r;
        const int i0 = ti * 8, j0 = tj * 8;

        const int ig = b * 4 + (i0 >> 6);
        const int jg = b * 4 + (j0 >> 6);
        if (tid == 0) {
            while (ld_acq(&g_cnt[ig]) < 24) __nanosleep(64);
            while (ld_acq(&g_cnt[jg]) < 24) __nanosleep(64);
        }
        __syncthreads();

        // stage 8 v rows (sum of both split-K planes)
#pragma unroll
        for (int el = tid; el < 8 * V4; el += 256) {
            int rr = el / V4, cc = el - rr * V4;
            size_t off = (size_t)(b * SS + j0 + rr) * N2 + HH;
            float4 v0 = ((const float4*)(g_gv[0] + off))[cc];
            float4 v1 = ((const float4*)(g_gv[1] + off))[cc];
            float4 s;
            s.x = v0.x + v1.x; s.y = v0.y + v1.y;
            s.z = v0.z + v1.z; s.w = v0.w + v1.w;
            ((float4*)vs)[el] = s;
        }

        // g row for this warp -> registers (bias folded into plane 0)
        const int i = i0 + wid;
        size_t goff = (size_t)(b * SS + i) * N2;
        const float4* g0 = (const float4*)(g_gv[0] + goff);
        const float4* g1 = (const float4*)(g_gv[1] + goff);
        float4 gr4[6];
#pragma unroll
        for (int qq = 0; qq < 6; qq++) {
            float4 a = g0[lane + qq * 32], c = g1[lane + qq * 32];
            gr4[qq].x = a.x + c.x; gr4[qq].y = a.y + c.y;
            gr4[qq].z = a.z + c.z; gr4[qq].w = a.w + c.w;
        }

        __syncthreads();

        const int pbase = i * SS - ((i * (i - 1)) >> 1) - i;  // p = pbase + j

        for (int lj = 0; lj < 8; ++lj) {
            const int j = j0 + lj;
            if (j < i) continue;
            const float4* vp = (const float4*)(vs + lj * HH);
            float4* op = (float4*)(out + ((size_t)b * NPAIR + pbase + j) * HH);
#pragma unroll
            for (int qq = 0; qq < 6; qq++) {
                const int vv = lane + qq * 32;
                float4 v4 = vp[vv];
                float4 o;
                o.x = fast_tanh(gr4[qq].x + v4.x);
                o.y = fast_tanh(gr4[qq].y + v4.y);
                o.z = fast_tanh(gr4[qq].z + v4.z);
                o.w = fast_tanh(gr4[qq].w + v4.w);
                __stcs(op + vv, o);
            }
        }
    }
}

extern "C" void kernel_launch(void* const* d_in, const int* in_sizes, int n_in,
                              void* d_out, int out_size)
{
    const float* x    = (const float*)d_in[0];
    const float* W    = (const float*)d_in[1];
    const float* bias = (const float*)d_in[2];
    float* out = (float*)d_out;

    static int init = 0;
    if (!init) {
        cudaFuncSetAttribute(fused_kernel, cudaFuncAttributeMaxDynamicSharedMemorySize,
                             GEMM_SMEM);
        init = 1;
    }

    convert_kernel<<<1920, 256>>>(x, W);
    fused_kernel<<<BB * BLK, 256, GEMM_SMEM>>>(bias, out);
}

// round 16
// speedup vs baseline: 1.0114x; 1.0114x over previous
#include <cuda_runtime.h>
#include <cuda_bf16.h>
#include <cstdint>

#define BB 4
#define SS 256
#define HH 768
#define N2 1536
#define MM 1024
#define NPAIR 32896

// GEMM tiling: BM=64, BN=128, split-K=2 (each producer CTA does K=384)
#define BM 64
#define BN 128
#define BK 32
#define RS 40                   // smem row stride in bf16 elems (80B, padded, conflict-free)
#define APLANE (BM * RS)        // 2560
#define BPLANE (BN * RS)        // 5120
#define BUFSZ (2 * APLANE + 2 * BPLANE)   // 15360 elems (30720 B) per buffer
#define NCH 12                  // chunks per K-split (384/32)
#define GEMM_SMEM (2 * BUFSZ * (int)sizeof(uint16_t))   // 61440 B
#define NTILE 528               // per-batch upper-triangular 8x8 tile count
#define BLK (96 + NTILE)        // bids per batch block: 96 producers + 528 consumers

__device__ float g_gv[2][MM * N2];      // two split-K planes; [m][0:768)=g, [768:)=v
__device__ int g_cnt[16];               // per (batch, 64-row group) counters, target 24
__device__ __nv_bfloat16 g_Ahi[MM * HH];
__device__ __nv_bfloat16 g_Alo[MM * HH];
__device__ __nv_bfloat16 g_Bhi[N2 * HH];   // [n][k], n<768 -> Wg row, n>=768 -> Wv row
__device__ __nv_bfloat16 g_Blo[N2 * HH];

// ---------------------------------------------------------------------------
// helpers
// ---------------------------------------------------------------------------
__device__ __forceinline__ uint32_t smem_u32(const void* p) {
    uint32_t a;
    asm("{ .reg .u64 t; cvta.to.shared.u64 t, %1; cvt.u32.u64 %0, t; }" : "=r"(a) : "l"(p));
    return a;
}

__device__ __forceinline__ void cp16(uint32_t dst, const void* src) {
    asm volatile("cp.async.cg.shared.global [%0], [%1], 16;" :: "r"(dst), "l"(src));
}
#define CP_COMMIT() asm volatile("cp.async.commit_group;" ::: "memory")
#define CP_WAIT1()  asm volatile("cp.async.wait_group 1;" ::: "memory")
#define CP_WAIT0()  asm volatile("cp.async.wait_group 0;" ::: "memory")

__device__ __forceinline__ void ldsm_x4(uint32_t* r, uint32_t addr) {
    asm volatile("ldmatrix.sync.aligned.m8n8.x4.shared.b16 {%0,%1,%2,%3}, [%4];"
                 : "=r"(r[0]), "=r"(r[1]), "=r"(r[2]), "=r"(r[3]) : "r"(addr));
}

__device__ __forceinline__ void mma16816(float* c, const uint32_t* a, const uint32_t* b) {
    asm volatile(
        "mma.sync.aligned.m16n8k16.row.col.f32.bf16.bf16.f32 "
        "{%0,%1,%2,%3}, {%4,%5,%6,%7}, {%8,%9}, {%0,%1,%2,%3};"
        : "+f"(c[0]), "+f"(c[1]), "+f"(c[2]), "+f"(c[3])
        : "r"(a[0]), "r"(a[1]), "r"(a[2]), "r"(a[3]), "r"(b[0]), "r"(b[1]));
}

__device__ __forceinline__ float fast_tanh(float x) {
    float y;
    asm("tanh.approx.f32 %0, %1;" : "=f"(y) : "f"(x));
    return y;
}

__device__ __forceinline__ int ld_acq(const int* p) {
    int v;
    asm volatile("ld.acquire.gpu.b32 %0, [%1];" : "=r"(v) : "l"(p) : "memory");
    return v;
}

__device__ __forceinline__ void split_pack(float a, float b, uint32_t& hi, uint32_t& lo) {
    asm("cvt.rn.bf16x2.f32 %0, %1, %2;" : "=r"(hi) : "f"(b), "f"(a));
    float ha = __uint_as_float(hi << 16);
    float hb = __uint_as_float(hi & 0xffff0000u);
    asm("cvt.rn.bf16x2.f32 %0, %1, %2;" : "=r"(lo) : "f"(b - hb), "f"(a - ha));
}

// ---------------------------------------------------------------------------
// Convert: fp32 X,W -> bf16 hi/lo planes; also zero the sync counters.
// ---------------------------------------------------------------------------
__global__ __launch_bounds__(256) void convert_kernel(
    const float* __restrict__ X, const float* __restrict__ W)
{
    if (blockIdx.x == 0 && threadIdx.x < 16) g_cnt[threadIdx.x] = 0;

    const int NX4 = MM * HH / 4;   // 196608
    const int NW4 = N2 * HH / 4;   // 294912
    int i4 = blockIdx.x * blockDim.x + threadIdx.x;
    if (i4 < NX4) {
        float4 v = ((const float4*)X)[i4];
        uint2 hv, lv;
        split_pack(v.x, v.y, hv.x, lv.x);
        split_pack(v.z, v.w, hv.y, lv.y);
        ((uint2*)g_Ahi)[i4] = hv;
        ((uint2*)g_Alo)[i4] = lv;
    } else if (i4 < NX4 + NW4) {
        int w4 = i4 - NX4;
        int e = w4 * 4;
        int n = e / HH;
        int k = e - n * HH;
        int o    = (n < HH) ? n : n - HH;
        int coff = (n < HH) ? 0 : HH;
        float4 v = *(const float4*)(W + (size_t)o * N2 + coff + k);
        uint2 hv, lv;
        split_pack(v.x, v.y, hv.x, lv.x);
        split_pack(v.z, v.w, hv.y, lv.y);
        ((uint2*)g_Bhi)[w4] = hv;
        ((uint2*)g_Blo)[w4] = lv;
    }
}

// ---------------------------------------------------------------------------
// Fused kernel. Per batch block of 624 bids:
//   [0,96):  GEMM producers (split-K=2, cp.async pipeline, bf16 3-pass)
//   [96,624): expand consumers (one upper-tri 8x8 tile each)
// ---------------------------------------------------------------------------
__global__ __launch_bounds__(256, 3) void fused_kernel(
    const float* __restrict__ bias, float* __restrict__ out)
{
    extern __shared__ char smx[];
    const int bid = blockIdx.x;
    const int tid = threadIdx.x;
    const int lane = tid & 31, wid = tid >> 5;
    const int b = bid / BLK;
    const int p = bid % BLK;

    if (p < 96) {
        // ================= GEMM producer =================
        const uint32_t sbase = smem_u32(smx);

        const int ksp = p / 48;
        const int tt  = p % 48;
        const int mt  = tt / 12;
        const int nt  = tt % 12;
        const int m0  = b * SS + mt * BM;
        const int n0  = nt * BN;
        const int kb0 = ksp * 384;
        const int side = (n0 >= HH) ? 1 : 0;

        const int mwB = (wid >> 2) * 32;
        const int nwB = (wid & 3) * 32;
        const int gr  = lane >> 2;
        const int gc  = (lane & 3) << 1;

        // ldmatrix lane addressing terms (bf16 elem units)
        const int lrow = lane & 7;
        const int q    = lane >> 3;
        int aTerm[2], bTerm[2];
#pragma unroll
        for (int m = 0; m < 2; m++)
            aTerm[m] = (mwB + m * 16 + (q & 1) * 8 + lrow) * RS + (q >> 1) * 8;
#pragma unroll
        for (int u = 0; u < 2; u++)
            bTerm[u] = (nwB + u * 16 + (q >> 1) * 8 + lrow) * RS + (q & 1) * 8;

        // cp.async slots: A (1 x16B per plane), B (2 x16B per plane)
        const int ar = tid >> 2, ac = tid & 3;
        const size_t aSrc = (size_t)(m0 + ar) * HH + kb0 + ac * 8;
        const uint32_t aDst = (uint32_t)(ar * RS + ac * 8) * 2;
        size_t bSrc[2];
        uint32_t bDst[2];
#pragma unroll
        for (int qq = 0; qq < 2; qq++) {
            int f = qq * 256 + tid;
            int r = f >> 2, c = f & 3;
            bSrc[qq] = (size_t)(n0 + r) * HH + kb0 + c * 8;
            bDst[qq] = (uint32_t)(r * RS + c * 8) * 2;
        }

        float acc[2][4][4] = {};

        // pipeline: issue chunk0
        {
            const uint32_t base = sbase;
            cp16(base + aDst, g_Ahi + aSrc);
            cp16(base + APLANE * 2 + aDst, g_Alo + aSrc);
#pragma unroll
            for (int qq = 0; qq < 2; qq++) {
                cp16(base + 2 * APLANE * 2 + bDst[qq], g_Bhi + bSrc[qq]);
                cp16(base + (2 * APLANE + BPLANE) * 2 + bDst[qq], g_Blo + bSrc[qq]);
            }
            CP_COMMIT();
        }

#pragma unroll 1
        for (int ch = 0; ch < NCH; ch++) {
            if (ch < NCH - 1) {
                const int ka = (ch + 1) * BK;
                const uint32_t base = sbase + (uint32_t)(((ch + 1) & 1) * BUFSZ) * 2;
                cp16(base + aDst, g_Ahi + aSrc + ka);
                cp16(base + APLANE * 2 + aDst, g_Alo + aSrc + ka);
#pragma unroll
                for (int qq = 0; qq < 2; qq++) {
                    cp16(base + 2 * APLANE * 2 + bDst[qq], g_Bhi + bSrc[qq] + ka);
                    cp16(base + (2 * APLANE + BPLANE) * 2 + bDst[qq], g_Blo + bSrc[qq] + ka);
                }
                CP_COMMIT();
                CP_WAIT1();
            } else {
                CP_WAIT0();
            }
            __syncthreads();

            const uint32_t Ah = sbase + (uint32_t)((ch & 1) * BUFSZ) * 2;
            const uint32_t Al = Ah + APLANE * 2;
            const uint32_t Bh = Al + APLANE * 2;
            const uint32_t Bl = Bh + BPLANE * 2;

#pragma unroll
            for (int ks = 0; ks < 2; ks++) {
                const uint32_t kbb = (uint32_t)(ks * 16) * 2;
                uint32_t ahi[2][4], bx[4][2], t4[4];
                // ahi + bhi, then mma; reload bx for blo; alo last (low live range)
#pragma unroll
                for (int m = 0; m < 2; m++)
                    ldsm_x4(ahi[m], Ah + (uint32_t)aTerm[m] * 2 + kbb);
#pragma unroll
                for (int u = 0; u < 2; u++) {
                    ldsm_x4(t4, Bh + (uint32_t)bTerm[u] * 2 + kbb);
                    bx[2 * u][0] = t4[0]; bx[2 * u][1] = t4[1];
                    bx[2 * u + 1][0] = t4[2]; bx[2 * u + 1][1] = t4[3];
                }
#pragma unroll
                for (int m = 0; m < 2; m++)
#pragma unroll
                    for (int n = 0; n < 4; n++) mma16816(acc[m][n], ahi[m], bx[n]);

                // alo x bhi (bx still holds bhi)
                {
                    uint32_t alo[4];
#pragma unroll
                    for (int m = 0; m < 2; m++) {
                        ldsm_x4(alo, Al + (uint32_t)aTerm[m] * 2 + kbb);
#pragma unroll
                        for (int n = 0; n < 4; n++) mma16816(acc[m][n], alo, bx[n]);
                    }
                }

                // ahi x blo (reload bx with blo)
#pragma unroll
                for (int u = 0; u < 2; u++) {
                    ldsm_x4(t4, Bl + (uint32_t)bTerm[u] * 2 + kbb);
                    bx[2 * u][0] = t4[0]; bx[2 * u][1] = t4[1];
                    bx[2 * u + 1][0] = t4[2]; bx[2 * u + 1][1] = t4[3];
                }
#pragma unroll
                for (int m = 0; m < 2; m++)
#pragma unroll
                    for (int n = 0; n < 4; n++) mma16816(acc[m][n], ahi[m], bx[n]);
            }
            __syncthreads();
        }

        // epilogue -> plane ksp; bias only on (g half, plane 0)
        float* plane = g_gv[ksp];
#pragma unroll
        for (int m = 0; m < 2; m++) {
#pragma unroll
            for (int n = 0; n < 4; n++) {
                const int r = m0 + mwB + m * 16 + gr;
                const int c = n0 + nwB + n * 8 + gc;
                float b0 = 0.f, b1 = 0.f;
                if (!side && ksp == 0) { b0 = bias[c]; b1 = bias[c + 1]; }
                float* pp = plane + (size_t)r * N2 + c;
                float2 v0, v1;
                v0.x = acc[m][n][0] + b0;
                v0.y = acc[m][n][1] + b1;
                v1.x = acc[m][n][2] + b0;
                v1.y = acc[m][n][3] + b1;
                *(float2*)pp = v0;
                *(float2*)(pp + 8 * N2) = v1;
            }
        }

        __threadfence();
        __syncthreads();
        if (tid == 0) atomicAdd(&g_cnt[b * 4 + mt], 1);

    } else {
        // ================= expand consumer =================
        constexpr int V4 = HH / 4;  // 192
        float* vs = (float*)smx;    // 8 rows * 768 floats = 24KB

        int r = p - 96;
        int ti = 0;
        while (r >= 32 - ti) { r -= 32 - ti; ti++; }
        const int tj = ti + r;
        const int i0 = ti * 8, j0 = tj * 8;

        const int ig = b * 4 + (i0 >> 6);
        const int jg = b * 4 + (j0 >> 6);
        if (tid == 0) {
            while (ld_acq(&g_cnt[ig]) < 24) __nanosleep(64);
            while (ld_acq(&g_cnt[jg]) < 24) __nanosleep(64);
        }
        __syncthreads();

        // stage 8 v rows (sum of both split-K planes)
#pragma unroll
        for (int el = tid; el < 8 * V4; el += 256) {
            int rr = el / V4, cc = el - rr * V4;
            size_t off = (size_t)(b * SS + j0 + rr) * N2 + HH;
            float4 v0 = ((const float4*)(g_gv[0] + off))[cc];
            float4 v1 = ((const float4*)(g_gv[1] + off))[cc];
            float4 s;
            s.x = v0.x + v1.x; s.y = v0.y + v1.y;
            s.z = v0.z + v1.z; s.w = v0.w + v1.w;
            ((float4*)vs)[el] = s;
        }

        // g row for this warp -> registers (bias folded into plane 0)
        const int i = i0 + wid;
        size_t goff = (size_t)(b * SS + i) * N2;
        const float4* g0 = (const float4*)(g_gv[0] + goff);
        const float4* g1 = (const float4*)(g_gv[1] + goff);
        float4 gr4[6];
#pragma unroll
        for (int qq = 0; qq < 6; qq++) {
            float4 a = g0[lane + qq * 32], c = g1[lane + qq * 32];
            gr4[qq].x = a.x + c.x; gr4[qq].y = a.y + c.y;
            gr4[qq].z = a.z + c.z; gr4[qq].w = a.w + c.w;
        }

        __syncthreads();

        const int pbase = i * SS - ((i * (i - 1)) >> 1) - i;  // p = pbase + j

        for (int lj = 0; lj < 8; ++lj) {
            const int j = j0 + lj;
            if (j < i) continue;
            const float4* vp = (const float4*)(vs + lj * HH);
            float4* op = (float4*)(out + ((size_t)b * NPAIR + pbase + j) * HH);
#pragma unroll
            for (int qq = 0; qq < 6; qq++) {
                const int vv = lane + qq * 32;
                float4 v4 = vp[vv];
                float4 o;
                o.x = fast_tanh(gr4[qq].x + v4.x);
                o.y = fast_tanh(gr4[qq].y + v4.y);
                o.z = fast_tanh(gr4[qq].z + v4.z);
                o.w = fast_tanh(gr4[qq].w + v4.w);
                __stcs(op + vv, o);
            }
        }
    }
}

extern "C" void kernel_launch(void* const* d_in, const int* in_sizes, int n_in,
                              void* d_out, int out_size)
{
    const float* x    = (const float*)d_in[0];
    const float* W    = (const float*)d_in[1];
    const float* bias = (const float*)d_in[2];
    float* out = (float*)d_out;

    static int init = 0;
    if (!init) {
        cudaFuncSetAttribute(fused_kernel, cudaFuncAttributeMaxDynamicSharedMemorySize,
                             GEMM_SMEM);
        init = 1;
    }

    convert_kernel<<<1920, 256>>>(x, W);
    fused_kernel<<<BB * BLK, 256, GEMM_SMEM>>>(bias, out);
}